// round 9
// baseline (speedup 1.0000x reference)
#include <cuda_runtime.h>
#include <cuda_fp16.h>
#include <cstdint>

#define NN   8192
#define FIN  256
#define FOUT 128
#define L2E  1.44269504f
#define LRA  0.2f
#define CK   128                   // j per chunk
#define JSPLIT 4
#define JBLK (NN / JSPLIT)         // 2048
#define NCH  (JBLK / CK)           // 16 chunks per block
#define RBLK 256                   // rows per block
#define NTI  (NN / 64)             // 128 prebuilt 64j B tiles
#define TB64 16384                 // one 64j tile: 64j x 128d x 2B
#define TILE_BYTES 32768           // per-chunk B buffer: 2 x 64j tiles
#define BITS_OFF (2 * TILE_BYTES)  // smem offset of ballot-bits buffer

__device__ __align__(16)  float g_h[NN * FOUT];
__device__ float g_e1s[NN];        // 1.4427 * e1
__device__ float g_e2s[NN];        // 1.4427 * e2
__device__ __align__(128) unsigned char g_bt[(size_t)NTI * TB64];        // 2MB
__device__ __align__(16)  float g_part[JSPLIT][NN * FOUT];               // 16MB
__device__ float g_psum[JSPLIT][NN];

// ------------------------- helpers -----------------------------------------
__device__ __forceinline__ uint32_t smem_u32(const void* p) {
    uint32_t a;
    asm("{ .reg .u64 t; cvta.to.shared.u64 t, %1; cvt.u32.u64 %0, t; }" : "=r"(a) : "l"(p));
    return a;
}
__device__ __forceinline__ uint32_t pack16(float lo, float hi) {
    uint32_t r;  // low 16 bits = lo (lower k index)
    asm("cvt.rn.f16x2.f32 %0, %1, %2;" : "=r"(r) : "f"(hi), "f"(lo));
    return r;
}
// pack two probs, mask with adjacency bits (we>>sh)&1 (low), (wo>>sh)&1 (high)
__device__ __forceinline__ uint32_t packm2(float lo, float hi,
                                           uint32_t we, uint32_t wo, int sh) {
    uint32_t p = pack16(lo, hi);
    uint32_t m = ((we >> sh) & 1u) * 0x3C00u + ((wo >> sh) & 1u) * 0x3C000000u;
    uint32_t r;
    asm("mul.f16x2 %0, %1, %2;" : "=r"(r) : "r"(p), "r"(m));
    return r;
}
__device__ __forceinline__ float pcalc(float se1, float se2) {
    float s = se1 + se2;
    s = fmaxf(s, LRA * s);          // lrelu commutes with positive scale
    float p;
    asm("ex2.approx.f32 %0, %1;" : "=f"(p) : "f"(s));
    return p;
}
__device__ __forceinline__ void mma16816(float* c, const uint32_t* a, const uint32_t* b) {
    asm volatile("mma.sync.aligned.m16n8k16.row.col.f32.f16.f16.f32 "
        "{%0,%1,%2,%3}, {%4,%5,%6,%7}, {%8,%9}, {%0,%1,%2,%3};"
        : "+f"(c[0]), "+f"(c[1]), "+f"(c[2]), "+f"(c[3])
        : "r"(a[0]), "r"(a[1]), "r"(a[2]), "r"(a[3]), "r"(b[0]), "r"(b[1]));
}
#define LDMX4(r, a) \
    asm volatile("ldmatrix.sync.aligned.m8n8.x4.shared.b16 {%0,%1,%2,%3}, [%4];" \
        : "=r"((r)[0]), "=r"((r)[1]), "=r"((r)[2]), "=r"((r)[3]) : "r"(a))
#define CP_ASYNC(dst, src) \
    asm volatile("cp.async.cg.shared.global [%0], [%1], 16;" :: "r"(dst), "l"(src))
#define CP_COMMIT() asm volatile("cp.async.commit_group;" ::: "memory")
#define CP_WAIT1()  asm volatile("cp.async.wait_group 1;"  ::: "memory")

// ---------------------------------------------------------------------------
// Kernel 1: h = x @ trans  (32-row tiles, 256 CTAs)
// ---------------------------------------------------------------------------
__global__ __launch_bounds__(256) void k_gemm_h(const float* __restrict__ x,
                                                const float* __restrict__ trans)
{
    __shared__ float xs[32 * 32];
    __shared__ float ts[32 * FOUT];
    const int t = threadIdx.x;
    const int rowbase = blockIdx.x * 32;
    const int ty = t >> 5;
    const int tx = t & 31;

    float acc[4][4];
    #pragma unroll
    for (int i = 0; i < 4; i++)
        #pragma unroll
        for (int c = 0; c < 4; c++) acc[i][c] = 0.f;

    const float4* x4 = (const float4*)x;
    const float4* t4 = (const float4*)trans;

    for (int k0 = 0; k0 < FIN; k0 += 32) {
        {
            int r = t >> 3, c = t & 7;
            ((float4*)xs)[r * 8 + c] = x4[(size_t)(rowbase + r) * (FIN/4) + (k0 >> 2) + c];
        }
        #pragma unroll
        for (int v = t, i = 0; i < 4; i++, v += 256) {
            int r = v >> 5, c = v & 31;
            ((float4*)ts)[r * 32 + c] = t4[(size_t)(k0 + r) * (FOUT/4) + c];
        }
        __syncthreads();
        #pragma unroll
        for (int kk = 0; kk < 32; kk++) {
            float4 b = *(const float4*)&ts[kk * FOUT + tx * 4];
            #pragma unroll
            for (int i = 0; i < 4; i++) {
                float a = xs[(ty * 4 + i) * 32 + kk];
                acc[i][0] += a * b.x; acc[i][1] += a * b.y;
                acc[i][2] += a * b.z; acc[i][3] += a * b.w;
            }
        }
        __syncthreads();
    }
    #pragma unroll
    for (int i = 0; i < 4; i++) {
        float4 o = make_float4(acc[i][0], acc[i][1], acc[i][2], acc[i][3]);
        *(float4*)&g_h[(size_t)(rowbase + ty * 4 + i) * FOUT + tx * 4] = o;
    }
}

// ---------------------------------------------------------------------------
// Kernel 2: e1/e2 (pre-scaled by log2(e))
// ---------------------------------------------------------------------------
__global__ __launch_bounds__(256) void k_e(const float* __restrict__ aw)
{
    const int row  = blockIdx.x * 8 + (threadIdx.x >> 5);
    const int lane = threadIdx.x & 31;
    float s1 = 0.f, s2 = 0.f;
    #pragma unroll
    for (int d = lane; d < FOUT; d += 32) {
        float v = g_h[(size_t)row * FOUT + d];
        s1 += v * aw[d];
        s2 += v * aw[FOUT + d];
    }
    #pragma unroll
    for (int o = 16; o; o >>= 1) {
        s1 += __shfl_xor_sync(0xFFFFFFFFu, s1, o);
        s2 += __shfl_xor_sync(0xFFFFFFFFu, s2, o);
    }
    if (lane == 0) { g_e1s[row] = s1 * L2E; g_e2s[row] = s2 * L2E; }
}

// ---------------------------------------------------------------------------
// Kernel 3 (prep): build B = h^T 64j tiles (fp16), ldmatrix-ready 8x8 blocks.
// blk = ((step*8+dpair)*2+dn)*2+kk; each blk = 128B: 8 rows (dr) x 8 j.
// Element (dr, jc) = h[j0+step*16+kk*8+jc][dp*16+dn*8+dr].
// ---------------------------------------------------------------------------
__global__ __launch_bounds__(256) void k_prep()
{
    const int tc = blockIdx.x;
    const int t  = threadIdx.x;
    const int j0 = tc * 64;
    unsigned char* tb = g_bt + (size_t)tc * TB64;

    #pragma unroll
    for (int i = 0; i < 4; i++) {
        int rho = i * 256 + t;
        int blk = rho >> 3, dr = rho & 7;
        int kk = blk & 1, dn = (blk >> 1) & 1, dp = (blk >> 2) & 7, st = blk >> 5;
        int d  = dp * 16 + dn * 8 + dr;
        int jb = j0 + st * 16 + kk * 8;
        uint32_t h4[4];
        #pragma unroll
        for (int m = 0; m < 4; m++) {
            float a = g_h[(size_t)(jb + 2*m)     * FOUT + d];
            float b = g_h[(size_t)(jb + 2*m + 1) * FOUT + d];
            h4[m] = pack16(a, b);
        }
        *(uint4*)(tb + (uint32_t)blk * 128 + dr * 16) =
            make_uint4(h4[0], h4[1], h4[2], h4[3]);
    }
}

// ---------------------------------------------------------------------------
// Kernel 4 (main): fused masked-exp + fp16 HMMA attention GEMM.
// 512 threads = 16 warps = 8 row-groups (m32) x 2 col-halves (n64).
// adj: in-kernel warp-cooperative coalesced int4 loads + ballot -> bit words
// in smem (per chunk); lane extracts its 16 mask bits with shifts.
// Row sums via ones-column MMA. B double-buffered (2x32KB) via cp.async.
// ---------------------------------------------------------------------------
__global__ __launch_bounds__(512, 1) void k_main(const int* __restrict__ adj)
{
    extern __shared__ unsigned char smem[];
    const uint32_t sb = smem_u32(smem);
    const int t = threadIdx.x, w = t >> 5, l = t & 31;
    const int rg = w >> 1, cg = w & 1;
    const int bx = blockIdx.x, by = blockIdx.y;
    const int g = l >> 2, qh = l & 3, q2 = qh * 2;
    const int rowb = bx * RBLK + rg * 32;
    const size_t jbase = (size_t)by * JBLK;
    const int hw = (qh & 1) * 2;      // even-j ballot word index
    const int bb = qh >> 1;           // bit offset within 4s group

    // prime B double-buffer (2 x 32KB; 512 threads x 4 vec16 per buffer)
    const unsigned char* bt0 = g_bt + (size_t)by * NCH * TILE_BYTES;
    #pragma unroll
    for (int c = 0; c < 2; c++) {
        uint32_t dst = sb + c * TILE_BYTES + t * 16;
        const unsigned char* src = bt0 + (size_t)c * TILE_BYTES + t * 16;
        #pragma unroll
        for (int i = 0; i < 4; i++) CP_ASYNC(dst + i * 8192, src + i * 8192);
        CP_COMMIT();
    }

    const float se1a = g_e1s[rowb + g];
    const float se1b = g_e1s[rowb + g + 8];
    const float se1c = g_e1s[rowb + g + 16];
    const float se1d = g_e1s[rowb + g + 24];

    float c0_[8][4], c1_[8][4];
    #pragma unroll
    for (int td = 0; td < 8; td++)
        #pragma unroll
        for (int k = 0; k < 4; k++) { c0_[td][k] = 0.f; c1_[td][k] = 0.f; }
    float crs0[4] = {0.f, 0.f, 0.f, 0.f};
    float crs1[4] = {0.f, 0.f, 0.f, 0.f};
    const uint32_t bones[2] = {0x3C003C00u, 0x3C003C00u};

    for (int c = 0; c < NCH; c++) {
        const size_t jgl = jbase + (size_t)c * CK;

        // ---- phase A: ballot-compress this warp's 16 adj rows (coalesced) ----
        // lane l loads adj[row][jgl + 4l .. 4l+3]; ballot word k bit l' <-> j = 4l'+k
        uint32_t W0 = 0, W1 = 0, W2 = 0, W3 = 0;
        #pragma unroll
        for (int i = 0; i < 16; i++) {
            const int4 av = __ldg((const int4*)(adj + (size_t)(rowb + cg * 16 + i) * NN + jgl) + l);
            uint32_t b0 = __ballot_sync(0xFFFFFFFFu, av.x != 0);
            uint32_t b1 = __ballot_sync(0xFFFFFFFFu, av.y != 0);
            uint32_t b2 = __ballot_sync(0xFFFFFFFFu, av.z != 0);
            uint32_t b3 = __ballot_sync(0xFFFFFFFFu, av.w != 0);
            W0 = (l == i) ? b0 : W0;
            W1 = (l == i) ? b1 : W1;
            W2 = (l == i) ? b2 : W2;
            W3 = (l == i) ? b3 : W3;
        }
        if (l < 16)
            *(uint4*)(smem + BITS_OFF + (rg * 32 + cg * 16 + l) * 16) =
                make_uint4(W0, W1, W2, W3);

        CP_WAIT1();
        __syncthreads();

        // lane's (even,odd) ballot words for its 4 rows
        const unsigned char* bp = smem + BITS_OFF + rg * 512 + hw * 4;
        const uint2 Wa = *(const uint2*)(bp + g * 16);
        const uint2 Wb = *(const uint2*)(bp + (g + 8) * 16);
        const uint2 Wc = *(const uint2*)(bp + (g + 16) * 16);
        const uint2 Wd = *(const uint2*)(bp + (g + 24) * 16);

        const uint32_t bufb = sb + (c & 1) * TILE_BYTES;

        #pragma unroll
        for (int s = 0; s < 8; s++) {
            const size_t joff = jgl + 16 * s + q2;
            const float2 e2a = *(const float2*)(g_e2s + joff);
            const float2 e2b = *(const float2*)(g_e2s + joff + 8);
            const int sh = 4 * s + bb;

            uint32_t a0[4], a1[4];
            a0[0] = packm2(pcalc(se1a, e2a.x), pcalc(se1a, e2a.y), Wa.x, Wa.y, sh);
            a0[1] = packm2(pcalc(se1b, e2a.x), pcalc(se1b, e2a.y), Wb.x, Wb.y, sh);
            a0[2] = packm2(pcalc(se1a, e2b.x), pcalc(se1a, e2b.y), Wa.x, Wa.y, sh + 2);
            a0[3] = packm2(pcalc(se1b, e2b.x), pcalc(se1b, e2b.y), Wb.x, Wb.y, sh + 2);
            a1[0] = packm2(pcalc(se1c, e2a.x), pcalc(se1c, e2a.y), Wc.x, Wc.y, sh);
            a1[1] = packm2(pcalc(se1d, e2a.x), pcalc(se1d, e2a.y), Wd.x, Wd.y, sh);
            a1[2] = packm2(pcalc(se1c, e2b.x), pcalc(se1c, e2b.y), Wc.x, Wc.y, sh + 2);
            a1[3] = packm2(pcalc(se1d, e2b.x), pcalc(se1d, e2b.y), Wd.x, Wd.y, sh + 2);

            #pragma unroll
            for (int dp = 0; dp < 4; dp++) {
                uint32_t bh[4];
                const uint32_t ad = bufb + (s >> 2) * TB64
                                  + ((s & 3) * 8 + cg * 4 + dp) * 512
                                  + (l >> 3) * 128 + (l & 7) * 16;
                LDMX4(bh, ad);
                mma16816(c0_[2 * dp],     a0, bh);
                mma16816(c0_[2 * dp + 1], a0, bh + 2);
                mma16816(c1_[2 * dp],     a1, bh);
                mma16816(c1_[2 * dp + 1], a1, bh + 2);
            }
            mma16816(crs0, a0, bones);
            mma16816(crs1, a1, bones);
        }

        __syncthreads();
        if (c + 2 < NCH) {
            uint32_t dst = sb + (c & 1) * TILE_BYTES + t * 16;
            const unsigned char* src = bt0 + (size_t)(c + 2) * TILE_BYTES + t * 16;
            #pragma unroll
            for (int i = 0; i < 4; i++) CP_ASYNC(dst + i * 8192, src + i * 8192);
        }
        CP_COMMIT();
    }

    // row sums (identical across n-cols and cg halves; cg==0 qh==0 writes)
    if (cg == 0 && qh == 0) {
        g_psum[by][rowb + g]      = crs0[0];
        g_psum[by][rowb + g + 8]  = crs0[2];
        g_psum[by][rowb + g + 16] = crs1[0];
        g_psum[by][rowb + g + 24] = crs1[2];
    }

    // store unnormalized partials (this warp's n64 half)
    float* pp = g_part[by];
    #pragma unroll
    for (int td = 0; td < 8; td++) {
        const int col = cg * 64 + td * 8 + q2;
        *(float2*)(pp + (size_t)(rowb + g) * FOUT + col) =
            make_float2(c0_[td][0], c0_[td][1]);
        *(float2*)(pp + (size_t)(rowb + g + 8) * FOUT + col) =
            make_float2(c0_[td][2], c0_[td][3]);
        *(float2*)(pp + (size_t)(rowb + g + 16) * FOUT + col) =
            make_float2(c1_[td][0], c1_[td][1]);
        *(float2*)(pp + (size_t)(rowb + g + 24) * FOUT + col) =
            make_float2(c1_[td][2], c1_[td][3]);
    }
}

// ---------------------------------------------------------------------------
// Kernel 5 (final): combine j-split partials, normalize, ELU.
// ---------------------------------------------------------------------------
__global__ __launch_bounds__(256) void k_final(float* __restrict__ out)
{
    const int idx = blockIdx.x * 256 + threadIdx.x;   // float4 index
    const int r = idx >> 5;
    float4 v = make_float4(0.f, 0.f, 0.f, 0.f);
    #pragma unroll
    for (int p = 0; p < JSPLIT; p++) {
        float4 a = ((const float4*)g_part[p])[idx];
        v.x += a.x; v.y += a.y; v.z += a.z; v.w += a.w;
    }
    const float inv = 1.f / (g_psum[0][r] + g_psum[1][r] + g_psum[2][r] + g_psum[3][r]);
    float o[4] = { v.x * inv, v.y * inv, v.z * inv, v.w * inv };
    #pragma unroll
    for (int i = 0; i < 4; i++) o[i] = o[i] > 0.f ? o[i] : expm1f(o[i]);
    ((float4*)out)[idx] = make_float4(o[0], o[1], o[2], o[3]);
}

// ---------------------------------------------------------------------------
extern "C" void kernel_launch(void* const* d_in, const int* in_sizes, int n_in,
                              void* d_out, int out_size)
{
    const float* x     = (const float*)d_in[0];
    const int*   adj   = (const int*)d_in[1];
    const float* trans = (const float*)d_in[2];
    const float* aw    = (const float*)d_in[3];
    float*       out   = (float*)d_out;

    const int smem_bytes = 2 * TILE_BYTES + 4096;   // B bufs + bits
    cudaFuncSetAttribute(k_main, cudaFuncAttributeMaxDynamicSharedMemorySize, smem_bytes);

    k_gemm_h<<<NN / 32, 256>>>(x, trans);
    k_e<<<NN / 8, 256>>>(aw);
    k_prep<<<NTI, 256>>>();
    dim3 gmain(NN / RBLK, JSPLIT);
    k_main<<<gmain, 512, smem_bytes>>>(adj);
    k_final<<<NN * FOUT / (256 * 4), 256>>>(out);
}

// round 10
// speedup vs baseline: 1.0870x; 1.0870x over previous
#include <cuda_runtime.h>
#include <cuda_fp16.h>
#include <cstdint>

#define NN   8192
#define FIN  256
#define FOUT 128
#define L2E  1.44269504f
#define LRA  0.2f
#define CK   128                   // j per chunk
#define JSPLIT 4
#define JBLK (NN / JSPLIT)         // 2048
#define NCH  (JBLK / CK)           // 16 chunks per block
#define RBLK 256                   // rows per block
#define NTI  (NN / 64)             // 128 prebuilt 64j B tiles
#define TB64 16384                 // one 64j tile: 64j x 128d x 2B
#define TILE_BYTES 32768           // per-chunk B buffer: 2 x 64j tiles
#define BITS_OFF (2 * TILE_BYTES)  // smem offset of bits buffer (256 rows x 16B)

__device__ __align__(16)  float g_h[NN * FOUT];
__device__ float g_e1s[NN];        // 1.4427 * e1
__device__ float g_e2s[NN];        // 1.4427 * e2
__device__ __align__(128) unsigned char g_bt[(size_t)NTI * TB64];        // 2MB
__device__ __align__(16)  float g_part[JSPLIT][NN * FOUT];               // 16MB
__device__ float g_psum[JSPLIT][NN];

// ------------------------- helpers -----------------------------------------
__device__ __forceinline__ uint32_t smem_u32(const void* p) {
    uint32_t a;
    asm("{ .reg .u64 t; cvta.to.shared.u64 t, %1; cvt.u32.u64 %0, t; }" : "=r"(a) : "l"(p));
    return a;
}
__device__ __forceinline__ uint32_t pack16(float lo, float hi) {
    uint32_t r;  // low 16 bits = lo (lower k index)
    asm("cvt.rn.f16x2.f32 %0, %1, %2;" : "=r"(r) : "f"(hi), "f"(lo));
    return r;
}
// pack two probs, mask with adjacency bits (we>>sh)&1 (lo), (wo>>sh)&1 (hi)
__device__ __forceinline__ uint32_t packm2(float lo, float hi,
                                           uint32_t we, uint32_t wo, int sh) {
    uint32_t p = pack16(lo, hi);
    uint32_t m = ((we >> sh) & 1u) * 0x3C00u + ((wo >> sh) & 1u) * 0x3C000000u;
    uint32_t r;
    asm("mul.f16x2 %0, %1, %2;" : "=r"(r) : "r"(p), "r"(m));
    return r;
}
__device__ __forceinline__ float pcalc(float se1, float se2) {
    float s = se1 + se2;
    s = fmaxf(s, LRA * s);          // lrelu commutes with positive scale
    float p;
    asm("ex2.approx.f32 %0, %1;" : "=f"(p) : "f"(s));
    return p;
}
__device__ __forceinline__ void mma16816(float* c, const uint32_t* a, const uint32_t* b) {
    asm volatile("mma.sync.aligned.m16n8k16.row.col.f32.f16.f16.f32 "
        "{%0,%1,%2,%3}, {%4,%5,%6,%7}, {%8,%9}, {%0,%1,%2,%3};"
        : "+f"(c[0]), "+f"(c[1]), "+f"(c[2]), "+f"(c[3])
        : "r"(a[0]), "r"(a[1]), "r"(a[2]), "r"(a[3]), "r"(b[0]), "r"(b[1]));
}
#define LDMX4(r, a) \
    asm volatile("ldmatrix.sync.aligned.m8n8.x4.shared.b16 {%0,%1,%2,%3}, [%4];" \
        : "=r"((r)[0]), "=r"((r)[1]), "=r"((r)[2]), "=r"((r)[3]) : "r"(a))
#define CP_ASYNC(dst, src) \
    asm volatile("cp.async.cg.shared.global [%0], [%1], 16;" :: "r"(dst), "l"(src))
#define CP_COMMIT() asm volatile("cp.async.commit_group;" ::: "memory")
#define CP_WAIT1()  asm volatile("cp.async.wait_group 1;"  ::: "memory")

// ---------------------------------------------------------------------------
// Kernel 1: h = x @ trans  (32-row tiles, 256 CTAs)
// ---------------------------------------------------------------------------
__global__ __launch_bounds__(256) void k_gemm_h(const float* __restrict__ x,
                                                const float* __restrict__ trans)
{
    __shared__ float xs[32 * 32];
    __shared__ float ts[32 * FOUT];
    const int t = threadIdx.x;
    const int rowbase = blockIdx.x * 32;
    const int ty = t >> 5;
    const int tx = t & 31;

    float acc[4][4];
    #pragma unroll
    for (int i = 0; i < 4; i++)
        #pragma unroll
        for (int c = 0; c < 4; c++) acc[i][c] = 0.f;

    const float4* x4 = (const float4*)x;
    const float4* t4 = (const float4*)trans;

    for (int k0 = 0; k0 < FIN; k0 += 32) {
        {
            int r = t >> 3, c = t & 7;
            ((float4*)xs)[r * 8 + c] = x4[(size_t)(rowbase + r) * (FIN/4) + (k0 >> 2) + c];
        }
        #pragma unroll
        for (int v = t, i = 0; i < 4; i++, v += 256) {
            int r = v >> 5, c = v & 31;
            ((float4*)ts)[r * 32 + c] = t4[(size_t)(k0 + r) * (FOUT/4) + c];
        }
        __syncthreads();
        #pragma unroll
        for (int kk = 0; kk < 32; kk++) {
            float4 b = *(const float4*)&ts[kk * FOUT + tx * 4];
            #pragma unroll
            for (int i = 0; i < 4; i++) {
                float a = xs[(ty * 4 + i) * 32 + kk];
                acc[i][0] += a * b.x; acc[i][1] += a * b.y;
                acc[i][2] += a * b.z; acc[i][3] += a * b.w;
            }
        }
        __syncthreads();
    }
    #pragma unroll
    for (int i = 0; i < 4; i++) {
        float4 o = make_float4(acc[i][0], acc[i][1], acc[i][2], acc[i][3]);
        *(float4*)&g_h[(size_t)(rowbase + ty * 4 + i) * FOUT + tx * 4] = o;
    }
}

// ---------------------------------------------------------------------------
// Kernel 2: e1/e2 (pre-scaled by log2(e))
// ---------------------------------------------------------------------------
__global__ __launch_bounds__(256) void k_e(const float* __restrict__ aw)
{
    const int row  = blockIdx.x * 8 + (threadIdx.x >> 5);
    const int lane = threadIdx.x & 31;
    float s1 = 0.f, s2 = 0.f;
    #pragma unroll
    for (int d = lane; d < FOUT; d += 32) {
        float v = g_h[(size_t)row * FOUT + d];
        s1 += v * aw[d];
        s2 += v * aw[FOUT + d];
    }
    #pragma unroll
    for (int o = 16; o; o >>= 1) {
        s1 += __shfl_xor_sync(0xFFFFFFFFu, s1, o);
        s2 += __shfl_xor_sync(0xFFFFFFFFu, s2, o);
    }
    if (lane == 0) { g_e1s[row] = s1 * L2E; g_e2s[row] = s2 * L2E; }
}

// ---------------------------------------------------------------------------
// Kernel 3 (prep): build B = h^T 64j tiles (fp16), ldmatrix-ready 8x8 blocks,
// WITH the j<->k remap: within a 16-k step, k = 2q+r (q=0..3) maps to
// j_local = 4q + r + 2*(k>=8). blk = ((step*8+dpair)*2+dn)*2+kk; pair m of
// row dr covers k = kk*8 + 2m + {0,1} -> j = step*16 + 4m + kk*2 + {0,1}.
// ---------------------------------------------------------------------------
__global__ __launch_bounds__(256) void k_prep()
{
    const int tc = blockIdx.x;
    const int t  = threadIdx.x;
    const int j0 = tc * 64;
    unsigned char* tb = g_bt + (size_t)tc * TB64;

    #pragma unroll
    for (int i = 0; i < 4; i++) {
        int rho = i * 256 + t;
        int blk = rho >> 3, dr = rho & 7;
        int kk = blk & 1, dn = (blk >> 1) & 1, dp = (blk >> 2) & 7, st = blk >> 5;
        int d  = dp * 16 + dn * 8 + dr;
        int jb = j0 + st * 16 + kk * 2;
        uint32_t h4[4];
        #pragma unroll
        for (int m = 0; m < 4; m++) {
            float a = g_h[(size_t)(jb + 4*m)     * FOUT + d];
            float b = g_h[(size_t)(jb + 4*m + 1) * FOUT + d];
            h4[m] = pack16(a, b);
        }
        *(uint4*)(tb + (uint32_t)blk * 128 + dr * 16) =
            make_uint4(h4[0], h4[1], h4[2], h4[3]);
    }
}

// ---------------------------------------------------------------------------
// Kernel 4 (main): fused masked-exp + fp16 HMMA attention GEMM.
// 512 threads = 16 warps = 8 row-groups (m32) x 2 col-halves (n64).
// Phase A per chunk: warp w ballot-compresses adj rows w*16..w*16+15 of the
// 128-j window (1 int4 LDG + 4 ballots + 1 predicated STS per row).
// Ballot word B_r bit l <-> j = 4l + r; with the j/k remap every lane's 4
// mask bits sit at shift (4s+qh) in the four words. e2 = one float4/step.
// Row sums via ones-column MMA. B double-buffered (2x32KB) via cp.async.
// ---------------------------------------------------------------------------
__global__ __launch_bounds__(512, 1) void k_main(const int* __restrict__ adj)
{
    extern __shared__ unsigned char smem[];
    const uint32_t sb = smem_u32(smem);
    const int t = threadIdx.x, w = t >> 5, l = t & 31;
    const int rg = w >> 1, cg = w & 1;
    const int bx = blockIdx.x, by = blockIdx.y;
    const int g = l >> 2, qh = l & 3;
    const int q2 = qh * 2;
    const int rowb = bx * RBLK + rg * 32;
    const size_t jbase = (size_t)by * JBLK;

    // prime B double-buffer (2 x 32KB; 512 threads x 4 vec16 per buffer)
    const unsigned char* bt0 = g_bt + (size_t)by * NCH * TILE_BYTES;
    #pragma unroll
    for (int c = 0; c < 2; c++) {
        uint32_t dst = sb + c * TILE_BYTES + t * 16;
        const unsigned char* src = bt0 + (size_t)c * TILE_BYTES + t * 16;
        #pragma unroll
        for (int i = 0; i < 4; i++) CP_ASYNC(dst + i * 8192, src + i * 8192);
        CP_COMMIT();
    }

    const float se1a = g_e1s[rowb + g];
    const float se1b = g_e1s[rowb + g + 8];
    const float se1c = g_e1s[rowb + g + 16];
    const float se1d = g_e1s[rowb + g + 24];

    float c0_[8][4], c1_[8][4];
    #pragma unroll
    for (int td = 0; td < 8; td++)
        #pragma unroll
        for (int k = 0; k < 4; k++) { c0_[td][k] = 0.f; c1_[td][k] = 0.f; }
    float crs0[4] = {0.f, 0.f, 0.f, 0.f};
    float crs1[4] = {0.f, 0.f, 0.f, 0.f};
    const uint32_t bones[2] = {0x3C003C00u, 0x3C003C00u};

    // phase-A row base for this warp (16 rows per warp covers the CTA's 256)
    const int arow = bx * RBLK + w * 16;

    for (int c = 0; c < NCH; c++) {
        const size_t jgl = jbase + (size_t)c * CK;

        // ---- phase A: ballot-compress 16 adj rows into smem bits ----
        #pragma unroll
        for (int i = 0; i < 16; i++) {
            const int4 av = __ldg((const int4*)(adj + (size_t)(arow + i) * NN + jgl) + l);
            uint32_t b0 = __ballot_sync(0xFFFFFFFFu, av.x != 0);
            uint32_t b1 = __ballot_sync(0xFFFFFFFFu, av.y != 0);
            uint32_t b2 = __ballot_sync(0xFFFFFFFFu, av.z != 0);
            uint32_t b3 = __ballot_sync(0xFFFFFFFFu, av.w != 0);
            if (l == i)
                *(uint4*)(smem + BITS_OFF + (w * 16 + i) * 16) =
                    make_uint4(b0, b1, b2, b3);
        }

        CP_WAIT1();
        __syncthreads();

        // bits for this lane's 4 rows (broadcast within each qh quad)
        const unsigned char* bp = smem + BITS_OFF + rg * 512;
        const uint4 Wa = *(const uint4*)(bp + g * 16);
        const uint4 Wb = *(const uint4*)(bp + (g + 8) * 16);
        const uint4 Wc = *(const uint4*)(bp + (g + 16) * 16);
        const uint4 Wd = *(const uint4*)(bp + (g + 24) * 16);

        const uint32_t bufb = sb + (c & 1) * TILE_BYTES;

        #pragma unroll
        for (int s = 0; s < 8; s++) {
            const float4 ev = *(const float4*)(g_e2s + jgl + 16 * s + 4 * qh);
            const int sh = 4 * s + qh;

            float pa0 = pcalc(se1a, ev.x), pa1 = pcalc(se1a, ev.y);
            float pa2 = pcalc(se1a, ev.z), pa3 = pcalc(se1a, ev.w);
            float pb0 = pcalc(se1b, ev.x), pb1 = pcalc(se1b, ev.y);
            float pb2 = pcalc(se1b, ev.z), pb3 = pcalc(se1b, ev.w);
            float pc0 = pcalc(se1c, ev.x), pc1 = pcalc(se1c, ev.y);
            float pc2 = pcalc(se1c, ev.z), pc3 = pcalc(se1c, ev.w);
            float pd0 = pcalc(se1d, ev.x), pd1 = pcalc(se1d, ev.y);
            float pd2 = pcalc(se1d, ev.z), pd3 = pcalc(se1d, ev.w);

            uint32_t a0[4], a1[4];
            a0[0] = packm2(pa0, pa1, Wa.x, Wa.y, sh);
            a0[1] = packm2(pb0, pb1, Wb.x, Wb.y, sh);
            a0[2] = packm2(pa2, pa3, Wa.z, Wa.w, sh);
            a0[3] = packm2(pb2, pb3, Wb.z, Wb.w, sh);
            a1[0] = packm2(pc0, pc1, Wc.x, Wc.y, sh);
            a1[1] = packm2(pd0, pd1, Wd.x, Wd.y, sh);
            a1[2] = packm2(pc2, pc3, Wc.z, Wc.w, sh);
            a1[3] = packm2(pd2, pd3, Wd.z, Wd.w, sh);

            #pragma unroll
            for (int dp = 0; dp < 4; dp++) {
                uint32_t bh[4];
                const uint32_t ad = bufb + (s >> 2) * TB64
                                  + ((s & 3) * 8 + cg * 4 + dp) * 512
                                  + (l >> 3) * 128 + (l & 7) * 16;
                LDMX4(bh, ad);
                mma16816(c0_[2 * dp],     a0, bh);
                mma16816(c0_[2 * dp + 1], a0, bh + 2);
                mma16816(c1_[2 * dp],     a1, bh);
                mma16816(c1_[2 * dp + 1], a1, bh + 2);
            }
            mma16816(crs0, a0, bones);
            mma16816(crs1, a1, bones);
        }

        __syncthreads();
        if (c + 2 < NCH) {
            uint32_t dst = sb + (c & 1) * TILE_BYTES + t * 16;
            const unsigned char* src = bt0 + (size_t)(c + 2) * TILE_BYTES + t * 16;
            #pragma unroll
            for (int i = 0; i < 4; i++) CP_ASYNC(dst + i * 8192, src + i * 8192);
        }
        CP_COMMIT();
    }

    // row sums (identical across n-cols and cg halves; cg==0 qh==0 writes)
    if (cg == 0 && qh == 0) {
        g_psum[by][rowb + g]      = crs0[0];
        g_psum[by][rowb + g + 8]  = crs0[2];
        g_psum[by][rowb + g + 16] = crs1[0];
        g_psum[by][rowb + g + 24] = crs1[2];
    }

    // store unnormalized partials (this warp's n64 half)
    float* pp = g_part[by];
    #pragma unroll
    for (int td = 0; td < 8; td++) {
        const int col = cg * 64 + td * 8 + q2;
        *(float2*)(pp + (size_t)(rowb + g) * FOUT + col) =
            make_float2(c0_[td][0], c0_[td][1]);
        *(float2*)(pp + (size_t)(rowb + g + 8) * FOUT + col) =
            make_float2(c0_[td][2], c0_[td][3]);
        *(float2*)(pp + (size_t)(rowb + g + 16) * FOUT + col) =
            make_float2(c1_[td][0], c1_[td][1]);
        *(float2*)(pp + (size_t)(rowb + g + 24) * FOUT + col) =
            make_float2(c1_[td][2], c1_[td][3]);
    }
}

// ---------------------------------------------------------------------------
// Kernel 5 (final): combine j-split partials, normalize, ELU.
// ---------------------------------------------------------------------------
__global__ __launch_bounds__(256) void k_final(float* __restrict__ out)
{
    const int idx = blockIdx.x * 256 + threadIdx.x;   // float4 index
    const int r = idx >> 5;
    float4 v = make_float4(0.f, 0.f, 0.f, 0.f);
    #pragma unroll
    for (int p = 0; p < JSPLIT; p++) {
        float4 a = ((const float4*)g_part[p])[idx];
        v.x += a.x; v.y += a.y; v.z += a.z; v.w += a.w;
    }
    const float inv = 1.f / (g_psum[0][r] + g_psum[1][r] + g_psum[2][r] + g_psum[3][r]);
    float o[4] = { v.x * inv, v.y * inv, v.z * inv, v.w * inv };
    #pragma unroll
    for (int i = 0; i < 4; i++) o[i] = o[i] > 0.f ? o[i] : expm1f(o[i]);
    ((float4*)out)[idx] = make_float4(o[0], o[1], o[2], o[3]);
}

// ---------------------------------------------------------------------------
extern "C" void kernel_launch(void* const* d_in, const int* in_sizes, int n_in,
                              void* d_out, int out_size)
{
    const float* x     = (const float*)d_in[0];
    const int*   adj   = (const int*)d_in[1];
    const float* trans = (const float*)d_in[2];
    const float* aw    = (const float*)d_in[3];
    float*       out   = (float*)d_out;

    const int smem_bytes = 2 * TILE_BYTES + 4096;   // B bufs + bits
    cudaFuncSetAttribute(k_main, cudaFuncAttributeMaxDynamicSharedMemorySize, smem_bytes);

    k_gemm_h<<<NN / 32, 256>>>(x, trans);
    k_e<<<NN / 8, 256>>>(aw);
    k_prep<<<NTI, 256>>>();
    dim3 gmain(NN / RBLK, JSPLIT);
    k_main<<<gmain, 512, smem_bytes>>>(adj);
    k_final<<<NN * FOUT / (256 * 4), 256>>>(out);
}

// round 11
// speedup vs baseline: 1.6684x; 1.5349x over previous
#include <cuda_runtime.h>
#include <cuda_fp16.h>
#include <cstdint>

#define NN   8192
#define FIN  256
#define FOUT 128
#define L2E  1.44269504f
#define LRA  0.2f
#define CK   64                    // j per chunk
#define JSPLIT 4
#define JBLK (NN / JSPLIT)         // 2048
#define NCH  (JBLK / CK)           // 32 chunks per block
#define RBLK 256                   // rows per block
#define NTI  (NN / CK)             // 128 prebuilt B tiles
#define TILE_BYTES 16384           // 64j x 128d x 2B

__device__ __align__(16)  float g_h[NN * FOUT];
__device__ float g_e1s[NN];        // 1.4427 * e1
__device__ float g_e2s[NN];        // 1.4427 * e2
__device__ __align__(128) unsigned char g_bt[(size_t)NTI * TILE_BYTES];  // 2MB
__device__ __align__(16)  float g_part[JSPLIT][NN * FOUT];               // 16MB
__device__ float g_psum[JSPLIT][NN];

// ------------------------- helpers -----------------------------------------
__device__ __forceinline__ uint32_t smem_u32(const void* p) {
    uint32_t a;
    asm("{ .reg .u64 t; cvta.to.shared.u64 t, %1; cvt.u32.u64 %0, t; }" : "=r"(a) : "l"(p));
    return a;
}
__device__ __forceinline__ uint32_t pack16(float lo, float hi) {
    uint32_t r;  // low 16 bits = lo (lower k index)
    asm("cvt.rn.f16x2.f32 %0, %1, %2;" : "=r"(r) : "f"(hi), "f"(lo));
    return r;
}
// mask-multiply: adj ints (0/1) -> fp16x2 {0,1} mask via 2 IMADs, one mul.f16x2
__device__ __forceinline__ uint32_t packmask(float lo, float hi, int ax, int ay) {
    uint32_t p = pack16(lo, hi);
    uint32_t m = (uint32_t)ax * 0x3C00u + (uint32_t)ay * 0x3C000000u;
    uint32_t r;
    asm("mul.f16x2 %0, %1, %2;" : "=r"(r) : "r"(p), "r"(m));
    return r;
}
__device__ __forceinline__ float pcalc(float se1, float se2) {
    float s = se1 + se2;
    s = fmaxf(s, LRA * s);          // lrelu commutes with positive scale
    float p;
    asm("ex2.approx.f32 %0, %1;" : "=f"(p) : "f"(s));
    return p;
}
__device__ __forceinline__ void mma16816(float* c, const uint32_t* a, const uint32_t* b) {
    asm volatile("mma.sync.aligned.m16n8k16.row.col.f32.f16.f16.f32 "
        "{%0,%1,%2,%3}, {%4,%5,%6,%7}, {%8,%9}, {%0,%1,%2,%3};"
        : "+f"(c[0]), "+f"(c[1]), "+f"(c[2]), "+f"(c[3])
        : "r"(a[0]), "r"(a[1]), "r"(a[2]), "r"(a[3]), "r"(b[0]), "r"(b[1]));
}
#define LDMX4(r, a) \
    asm volatile("ldmatrix.sync.aligned.m8n8.x4.shared.b16 {%0,%1,%2,%3}, [%4];" \
        : "=r"((r)[0]), "=r"((r)[1]), "=r"((r)[2]), "=r"((r)[3]) : "r"(a))
#define CP_ASYNC(dst, src) \
    asm volatile("cp.async.cg.shared.global [%0], [%1], 16;" :: "r"(dst), "l"(src))
#define CP_COMMIT() asm volatile("cp.async.commit_group;" ::: "memory")
#define CP_WAIT1()  asm volatile("cp.async.wait_group 1;"  ::: "memory")

// ---------------------------------------------------------------------------
// Kernel 1: h = x @ trans  (32-row tiles, 256 CTAs) + fused e1/e2 epilogue
// ---------------------------------------------------------------------------
__global__ __launch_bounds__(256) void k_gemm_h(const float* __restrict__ x,
                                                const float* __restrict__ trans,
                                                const float* __restrict__ aw)
{
    __shared__ float xs[32 * 32];
    __shared__ float ts[32 * FOUT];
    const int t = threadIdx.x;
    const int rowbase = blockIdx.x * 32;
    const int ty = t >> 5;
    const int tx = t & 31;

    float acc[4][4];
    #pragma unroll
    for (int i = 0; i < 4; i++)
        #pragma unroll
        for (int c = 0; c < 4; c++) acc[i][c] = 0.f;

    const float4* x4 = (const float4*)x;
    const float4* t4 = (const float4*)trans;

    for (int k0 = 0; k0 < FIN; k0 += 32) {
        {
            int r = t >> 3, c = t & 7;
            ((float4*)xs)[r * 8 + c] = x4[(size_t)(rowbase + r) * (FIN/4) + (k0 >> 2) + c];
        }
        #pragma unroll
        for (int v = t, i = 0; i < 4; i++, v += 256) {
            int r = v >> 5, c = v & 31;
            ((float4*)ts)[r * 32 + c] = t4[(size_t)(k0 + r) * (FOUT/4) + c];
        }
        __syncthreads();
        #pragma unroll
        for (int kk = 0; kk < 32; kk++) {
            float4 b = *(const float4*)&ts[kk * FOUT + tx * 4];
            #pragma unroll
            for (int i = 0; i < 4; i++) {
                float a = xs[(ty * 4 + i) * 32 + kk];
                acc[i][0] += a * b.x; acc[i][1] += a * b.y;
                acc[i][2] += a * b.z; acc[i][3] += a * b.w;
            }
        }
        __syncthreads();
    }
    const float4 w1 = __ldg((const float4*)(aw) + tx);
    const float4 w2 = __ldg((const float4*)(aw + FOUT) + tx);
    #pragma unroll
    for (int i = 0; i < 4; i++) {
        float4 o = make_float4(acc[i][0], acc[i][1], acc[i][2], acc[i][3]);
        *(float4*)&g_h[(size_t)(rowbase + ty * 4 + i) * FOUT + tx * 4] = o;
        // fused e1/e2: this warp owns the full row
        float s1 = o.x * w1.x + o.y * w1.y + o.z * w1.z + o.w * w1.w;
        float s2 = o.x * w2.x + o.y * w2.y + o.z * w2.z + o.w * w2.w;
        #pragma unroll
        for (int off = 16; off; off >>= 1) {
            s1 += __shfl_xor_sync(0xFFFFFFFFu, s1, off);
            s2 += __shfl_xor_sync(0xFFFFFFFFu, s2, off);
        }
        if (tx == 0) {
            g_e1s[rowbase + ty * 4 + i] = s1 * L2E;
            g_e2s[rowbase + ty * 4 + i] = s2 * L2E;
        }
    }
}

// ---------------------------------------------------------------------------
// Kernel 3 (prep): build B = h^T 64j tiles (fp16), ldmatrix-ready 8x8 blocks,
// WITH the j<->k remap: pair m of row dr in block (st,dp,dn,kk) covers
// k = kk*8 + 2m + {0,1} -> j = st*16 + 4m + kk*2 + {0,1}.   (verified R10)
// 256 CTAs: bx>>1 = tile, bx&1 = half.
// ---------------------------------------------------------------------------
__global__ __launch_bounds__(256) void k_prep()
{
    const int tc = blockIdx.x >> 1;
    const int hf = blockIdx.x & 1;
    const int t  = threadIdx.x;
    const int j0 = tc * CK;
    unsigned char* tb = g_bt + (size_t)tc * TILE_BYTES;

    #pragma unroll
    for (int i = 0; i < 2; i++) {
        int rho = (hf * 2 + i) * 256 + t;
        int blk = rho >> 3, dr = rho & 7;
        int kk = blk & 1, dn = (blk >> 1) & 1, dp = (blk >> 2) & 7, st = blk >> 5;
        int d  = dp * 16 + dn * 8 + dr;
        int jb = j0 + st * 16 + kk * 2;
        uint32_t h4[4];
        #pragma unroll
        for (int m = 0; m < 4; m++) {
            float a = g_h[(size_t)(jb + 4*m)     * FOUT + d];
            float b = g_h[(size_t)(jb + 4*m + 1) * FOUT + d];
            h4[m] = pack16(a, b);
        }
        *(uint4*)(tb + (uint32_t)blk * 128 + dr * 16) =
            make_uint4(h4[0], h4[1], h4[2], h4[3]);
    }
}

// ---------------------------------------------------------------------------
// Kernel 4 (main): fused masked-exp + fp16 HMMA attention GEMM (R6 structure).
// 512 threads = 16 warps of m16 x n128. j<->k remap makes each lane's 4
// adjacency flags ONE contiguous int4 and e2 ONE float4 per step.
// Masks: 2 IMAD + mul.f16x2 (no shifts/ballots). Row sums via ones-MMA.
// B (remapped h^T fp16) double-buffered via cp.async + ldmatrix.x4.
// ---------------------------------------------------------------------------
__global__ __launch_bounds__(512, 1) void k_main(const int* __restrict__ adj)
{
    extern __shared__ unsigned char smem[];
    const uint32_t sb = smem_u32(smem);
    const int t = threadIdx.x, w = t >> 5, l = t & 31;
    const int bx = blockIdx.x, by = blockIdx.y;
    const int g = l >> 2, qh = l & 3, q2 = qh * 2;
    const int rowb = bx * RBLK + w * 16;
    const size_t jbase = (size_t)by * JBLK;

    // prime B double-buffer (2 x 16KB; 512 threads x 2 vec16 per buffer)
    const unsigned char* bt0 = g_bt + (size_t)(by * NCH) * TILE_BYTES;
    #pragma unroll
    for (int c = 0; c < 2; c++) {
        uint32_t dst = sb + c * TILE_BYTES + t * 16;
        const unsigned char* src = bt0 + (size_t)c * TILE_BYTES + t * 16;
        CP_ASYNC(dst, src);
        CP_ASYNC(dst + 8192, src + 8192);
        CP_COMMIT();
    }

    const float se1g = g_e1s[rowb + g];
    const float se1h = g_e1s[rowb + g + 8];
    const int* pg = adj + (size_t)(rowb + g) * NN + jbase;
    const int* ph = adj + (size_t)(rowb + g + 8) * NN + jbase;

    float c_[16][4];
    #pragma unroll
    for (int td = 0; td < 16; td++)
        #pragma unroll
        for (int k = 0; k < 4; k++) c_[td][k] = 0.f;
    float crs[4] = {0.f, 0.f, 0.f, 0.f};
    const uint32_t bones[2] = {0x3C003C00u, 0x3C003C00u};

    // adj prefetch for (c=0, s=0): one int4 per row (j = 4qh..4qh+3)
    int joff = 4 * qh;
    int4 avg = __ldg((const int4*)(pg + joff));
    int4 avh = __ldg((const int4*)(ph + joff));

    for (int c = 0; c < NCH; c++) {
        CP_WAIT1();
        __syncthreads();
        const uint32_t bufb = sb + (c & 1) * TILE_BYTES;

        #pragma unroll
        for (int s = 0; s < 4; s++) {
            const float4 ev = *(const float4*)(g_e2s + jbase + joff);

            // snapshot adj regs, then prefetch next step early
            const int4 bg = avg, bh_ = avh;
            if (!(c == NCH - 1 && s == 3)) {
                joff += 16;
                avg = __ldg((const int4*)(pg + joff));
                avh = __ldg((const int4*)(ph + joff));
            }

            float pa0 = pcalc(se1g, ev.x), pa1 = pcalc(se1g, ev.y);
            float pa2 = pcalc(se1g, ev.z), pa3 = pcalc(se1g, ev.w);
            float pb0 = pcalc(se1h, ev.x), pb1 = pcalc(se1h, ev.y);
            float pb2 = pcalc(se1h, ev.z), pb3 = pcalc(se1h, ev.w);

            uint32_t a[4];
            a[0] = packmask(pa0, pa1, bg.x, bg.y);
            a[1] = packmask(pb0, pb1, bh_.x, bh_.y);
            a[2] = packmask(pa2, pa3, bg.z, bg.w);
            a[3] = packmask(pb2, pb3, bh_.z, bh_.w);

            #pragma unroll
            for (int dp = 0; dp < 8; dp++) {
                uint32_t bh[4];
                const uint32_t ad = bufb + (s * 8 + dp) * 512
                                  + (l >> 3) * 128 + (l & 7) * 16;
                LDMX4(bh, ad);
                mma16816(c_[2 * dp],     a, bh);
                mma16816(c_[2 * dp + 1], a, bh + 2);
            }
            mma16816(crs, a, bones);   // row-sum column
        }

        __syncthreads();
        if (c + 2 < NCH) {
            uint32_t dst = sb + (c & 1) * TILE_BYTES + t * 16;
            const unsigned char* src = bt0 + (size_t)(c + 2) * TILE_BYTES + t * 16;
            CP_ASYNC(dst, src);
            CP_ASYNC(dst + 8192, src + 8192);
        }
        CP_COMMIT();
    }

    // row sums (all n8 cols identical in crs; qh==0 lanes write)
    if (qh == 0) {
        g_psum[by][rowb + g]     = crs[0];
        g_psum[by][rowb + g + 8] = crs[2];
    }

    // store unnormalized partials
    float* pb = g_part[by];
    #pragma unroll
    for (int td = 0; td < 16; td++) {
        const int col = td * 8 + q2;
        *(float2*)(pb + (size_t)(rowb + g) * FOUT + col) =
            make_float2(c_[td][0], c_[td][1]);
        *(float2*)(pb + (size_t)(rowb + g + 8) * FOUT + col) =
            make_float2(c_[td][2], c_[td][3]);
    }
}

// ---------------------------------------------------------------------------
// Kernel 5 (final): combine j-split partials, normalize, ELU.
// ---------------------------------------------------------------------------
__global__ __launch_bounds__(256) void k_final(float* __restrict__ out)
{
    const int idx = blockIdx.x * 256 + threadIdx.x;   // float4 index
    const int r = idx >> 5;
    float4 v = make_float4(0.f, 0.f, 0.f, 0.f);
    #pragma unroll
    for (int p = 0; p < JSPLIT; p++) {
        float4 a = ((const float4*)g_part[p])[idx];
        v.x += a.x; v.y += a.y; v.z += a.z; v.w += a.w;
    }
    const float inv = 1.f / (g_psum[0][r] + g_psum[1][r] + g_psum[2][r] + g_psum[3][r]);
    float o[4] = { v.x * inv, v.y * inv, v.z * inv, v.w * inv };
    #pragma unroll
    for (int i = 0; i < 4; i++) o[i] = o[i] > 0.f ? o[i] : expm1f(o[i]);
    ((float4*)out)[idx] = make_float4(o[0], o[1], o[2], o[3]);
}

// ---------------------------------------------------------------------------
extern "C" void kernel_launch(void* const* d_in, const int* in_sizes, int n_in,
                              void* d_out, int out_size)
{
    const float* x     = (const float*)d_in[0];
    const int*   adj   = (const int*)d_in[1];
    const float* trans = (const float*)d_in[2];
    const float* aw    = (const float*)d_in[3];
    float*       out   = (float*)d_out;

    const int smem_bytes = 2 * TILE_BYTES;   // 32KB
    cudaFuncSetAttribute(k_main, cudaFuncAttributeMaxDynamicSharedMemorySize, smem_bytes);

    k_gemm_h<<<NN / 32, 256>>>(x, trans, aw);
    k_prep<<<2 * NTI, 256>>>();
    dim3 gmain(NN / RBLK, JSPLIT);
    k_main<<<gmain, 512, smem_bytes>>>(adj);
    k_final<<<NN * FOUT / (256 * 4), 256>>>(out);
}

// round 12
// speedup vs baseline: 1.9045x; 1.1415x over previous
#include <cuda_runtime.h>
#include <cuda_fp16.h>
#include <cstdint>

#define NN   8192
#define FIN  256
#define FOUT 128
#define L2E  1.44269504f
#define LRA  0.2f
#define CK   64                    // j per chunk (k_main)
#define JSPLIT 4
#define JBLK (NN / JSPLIT)         // 2048
#define NCH  (JBLK / CK)           // 32 chunks per block
#define NTI  (NN / CK)             // 128 B tiles
#define TILE_BYTES 16384           // 64j x 128d x 2B fp16
#define XA_TERM 4194304            // bytes per A-term (8192x256 bf16)
#define TB_TERM 65536              // bytes per trans-term (256x128 bf16)
#define HB 49152                   // k_hgemm smem half-buffer stride

__device__ float g_e1s[NN];        // 1.4427 * e1
__device__ float g_e2s[NN];        // 1.4427 * e2
__device__ __align__(128) unsigned char g_xa[2 * XA_TERM];               // 8MB
__device__ __align__(128) unsigned char g_tb[2 * TB_TERM];               // 128KB
__device__ __align__(128) unsigned char g_bt[(size_t)NTI * TILE_BYTES];  // 2MB
__device__ __align__(16)  float g_part[JSPLIT][NN * FOUT];               // 16MB
__device__ float g_psum[JSPLIT][NN];

// ------------------------- helpers -----------------------------------------
__device__ __forceinline__ uint32_t smem_u32(const void* p) {
    uint32_t a;
    asm("{ .reg .u64 t; cvta.to.shared.u64 t, %1; cvt.u32.u64 %0, t; }" : "=r"(a) : "l"(p));
    return a;
}
__device__ __forceinline__ uint32_t pack16(float lo, float hi) {   // fp16x2
    uint32_t r;
    asm("cvt.rn.f16x2.f32 %0, %1, %2;" : "=r"(r) : "f"(hi), "f"(lo));
    return r;
}
__device__ __forceinline__ uint32_t packbf(float lo, float hi) {   // bf16x2
    uint32_t r;
    asm("cvt.rn.bf16x2.f32 %0, %1, %2;" : "=r"(r) : "f"(hi), "f"(lo));
    return r;
}
__device__ __forceinline__ void splitbf(float a, float b, uint32_t& hi, uint32_t& lo) {
    hi = packbf(a, b);
    float ra = a - __uint_as_float(hi << 16);
    float rb = b - __uint_as_float(hi & 0xFFFF0000u);
    lo = packbf(ra, rb);
}
__device__ __forceinline__ uint32_t packmask(float lo, float hi, int ax, int ay) {
    uint32_t p = pack16(lo, hi);
    uint32_t m = (uint32_t)ax * 0x3C00u + (uint32_t)ay * 0x3C000000u;
    uint32_t r;
    asm("mul.f16x2 %0, %1, %2;" : "=r"(r) : "r"(p), "r"(m));
    return r;
}
__device__ __forceinline__ float pcalc(float se1, float se2) {
    float s = se1 + se2;
    s = fmaxf(s, LRA * s);
    float p;
    asm("ex2.approx.f32 %0, %1;" : "=f"(p) : "f"(s));
    return p;
}
__device__ __forceinline__ float ex2f(float s) {
    float p;
    asm("ex2.approx.f32 %0, %1;" : "=f"(p) : "f"(s));
    return p;
}
__device__ __forceinline__ void mma16816(float* c, const uint32_t* a, const uint32_t* b) {
    asm volatile("mma.sync.aligned.m16n8k16.row.col.f32.f16.f16.f32 "
        "{%0,%1,%2,%3}, {%4,%5,%6,%7}, {%8,%9}, {%0,%1,%2,%3};"
        : "+f"(c[0]), "+f"(c[1]), "+f"(c[2]), "+f"(c[3])
        : "r"(a[0]), "r"(a[1]), "r"(a[2]), "r"(a[3]), "r"(b[0]), "r"(b[1]));
}
__device__ __forceinline__ void mma_bf(float* c, const uint32_t* a, const uint32_t* b) {
    asm volatile("mma.sync.aligned.m16n8k16.row.col.f32.bf16.bf16.f32 "
        "{%0,%1,%2,%3}, {%4,%5,%6,%7}, {%8,%9}, {%0,%1,%2,%3};"
        : "+f"(c[0]), "+f"(c[1]), "+f"(c[2]), "+f"(c[3])
        : "r"(a[0]), "r"(a[1]), "r"(a[2]), "r"(a[3]), "r"(b[0]), "r"(b[1]));
}
#define LDMX4(r, a) \
    asm volatile("ldmatrix.sync.aligned.m8n8.x4.shared.b16 {%0,%1,%2,%3}, [%4];" \
        : "=r"((r)[0]), "=r"((r)[1]), "=r"((r)[2]), "=r"((r)[3]) : "r"(a))
#define CP_ASYNC(dst, src) \
    asm volatile("cp.async.cg.shared.global [%0], [%1], 16;" :: "r"(dst), "l"(src))
#define CP_COMMIT() asm volatile("cp.async.commit_group;" ::: "memory")
#define CP_WAIT1()  asm volatile("cp.async.wait_group 1;"  ::: "memory")

// ---------------------------------------------------------------------------
// Kernel 1 (cvt): x -> bf16 hi/lo A tiles; trans -> bf16 hi/lo B tiles.
// A tile (mt,ks): 4 blocks of 8x8 b16 in ldmatrix-A order:
//   blk0 rows 0-7 k0-7, blk1 rows 8-15 k0-7, blk2 rows 0-7 k8-15, blk3 rows 8-15 k8-15.
// B (trans) block order per (ks,dp): (dn0,kk0),(dn0,kk1),(dn1,kk0),(dn1,kk1),
//   element (dr,m) = trans[kb+2m(+1)][n] — matches k_main's proven consumption.
// ---------------------------------------------------------------------------
__global__ __launch_bounds__(256) void k_cvt(const float* __restrict__ x,
                                             const float* __restrict__ trans)
{
    const int bx = blockIdx.x, t = threadIdx.x;
    if (bx < 512) {
        const int mt = bx;
        #pragma unroll
        for (int i = 0; i < 2; i++) {
            int rho = i * 256 + t;
            int ks = rho >> 5, blk = (rho >> 3) & 3, dr = rho & 7;
            int row = mt * 16 + (blk & 1) * 8 + dr;
            int kb  = ks * 16 + (blk >> 1) * 8;
            const float4* xp = (const float4*)(x + (size_t)row * FIN + kb);
            float4 v0 = __ldg(xp), v1 = __ldg(xp + 1);
            uint32_t hi4[4], lo4[4];
            splitbf(v0.x, v0.y, hi4[0], lo4[0]);
            splitbf(v0.z, v0.w, hi4[1], lo4[1]);
            splitbf(v1.x, v1.y, hi4[2], lo4[2]);
            splitbf(v1.z, v1.w, hi4[3], lo4[3]);
            uint32_t off = (uint32_t)(mt * 16 + ks) * 512 + blk * 128 + dr * 16;
            *(uint4*)(g_xa + off)           = make_uint4(hi4[0], hi4[1], hi4[2], hi4[3]);
            *(uint4*)(g_xa + XA_TERM + off) = make_uint4(lo4[0], lo4[1], lo4[2], lo4[3]);
        }
    } else {
        const int ks = bx - 512;
        int dp = t >> 5, blk = (t >> 3) & 3, dr = t & 7;
        int kk = blk & 1, dn = blk >> 1;
        int n  = dp * 16 + dn * 8 + dr;
        int kb = ks * 16 + kk * 8;
        uint32_t hi4[4], lo4[4];
        #pragma unroll
        for (int m = 0; m < 4; m++) {
            float a = __ldg(trans + (size_t)(kb + 2*m)     * FOUT + n);
            float b = __ldg(trans + (size_t)(kb + 2*m + 1) * FOUT + n);
            splitbf(a, b, hi4[m], lo4[m]);
        }
        uint32_t off = (uint32_t)(ks * 8 + dp) * 512 + blk * 128 + dr * 16;
        *(uint4*)(g_tb + off)           = make_uint4(hi4[0], hi4[1], hi4[2], hi4[3]);
        *(uint4*)(g_tb + TB_TERM + off) = make_uint4(lo4[0], lo4[1], lo4[2], lo4[3]);
    }
}

// ---------------------------------------------------------------------------
// Kernel 2 (hgemm): h = x@trans via 3-term bf16 HMMA. Grid 128 CTAs x 64 rows.
// 8 warps: rg = w>>1 (m16), cg = w&1 (n64 half). K=256 in 4 chunks of 64,
// double-buffered. Epilogue: h tile -> smem; build the REMAPPED fp16 g_bt
// tile for this CTA's 64 j directly from smem (k_prep folded in); fused e1/e2.
// ---------------------------------------------------------------------------
__global__ __launch_bounds__(256) void k_hgemm(const float* __restrict__ aw)
{
    extern __shared__ unsigned char smem[];
    const uint32_t sb = smem_u32(smem);
    const int t = threadIdx.x, w = t >> 5, l = t & 31;
    const int rg = w >> 1, cg = w & 1;
    const int g = l >> 2, qh = l & 3, q2 = qh * 2;
    const int bx = blockIdx.x;

    // prime double buffer (2 kchunks)
    #pragma unroll
    for (int kc = 0; kc < 2; kc++) {
        const uint32_t bufb = sb + kc * HB;
        #pragma unroll
        for (int q = 0; q < 2; q++) {          // A: 512 vec16/term
            int idx = q * 256 + t;
            int mtl = idx >> 7, rem = idx & 127;
            const unsigned char* src = g_xa + (size_t)((bx*4 + mtl)*16 + kc*4) * 512 + rem*16;
            uint32_t dst = bufb + mtl * 2048 + rem * 16;
            CP_ASYNC(dst, src);
            CP_ASYNC(dst + 8192, src + XA_TERM);
        }
        #pragma unroll
        for (int q = 0; q < 4; q++) {          // B: 1024 vec16/term
            int idx = q * 256 + t;
            const unsigned char* src = g_tb + kc * 16384 + idx * 16;
            uint32_t dst = bufb + 16384 + idx * 16;
            CP_ASYNC(dst, src);
            CP_ASYNC(dst + 16384, src + TB_TERM);
        }
        CP_COMMIT();
    }

    float c_[8][4];
    #pragma unroll
    for (int td = 0; td < 8; td++)
        #pragma unroll
        for (int k = 0; k < 4; k++) c_[td][k] = 0.f;

    for (int kc = 0; kc < 4; kc++) {
        CP_WAIT1();
        __syncthreads();
        const uint32_t bufb = sb + (kc & 1) * HB;
        #pragma unroll
        for (int ksl = 0; ksl < 4; ksl++) {
            uint32_t ahi[4], alo[4];
            const uint32_t aad = bufb + rg * 2048 + ksl * 512
                               + (l >> 3) * 128 + (l & 7) * 16;
            LDMX4(ahi, aad);
            LDMX4(alo, aad + 8192);
            #pragma unroll
            for (int dpl = 0; dpl < 4; dpl++) {
                const int dp = cg * 4 + dpl;
                uint32_t bhi[4], blo[4];
                const uint32_t bad = bufb + 16384 + (ksl * 8 + dp) * 512
                                   + (l >> 3) * 128 + (l & 7) * 16;
                LDMX4(bhi, bad);
                LDMX4(blo, bad + 16384);
                mma_bf(c_[2*dpl],     ahi, bhi);
                mma_bf(c_[2*dpl + 1], ahi, bhi + 2);
                mma_bf(c_[2*dpl],     alo, bhi);
                mma_bf(c_[2*dpl + 1], alo, bhi + 2);
                mma_bf(c_[2*dpl],     ahi, blo);
                mma_bf(c_[2*dpl + 1], ahi, blo + 2);
            }
        }
        __syncthreads();
        if (kc + 2 < 4) {
            const int kn = kc + 2;
            const uint32_t bufb2 = sb + (kc & 1) * HB;
            #pragma unroll
            for (int q = 0; q < 2; q++) {
                int idx = q * 256 + t;
                int mtl = idx >> 7, rem = idx & 127;
                const unsigned char* src = g_xa + (size_t)((bx*4 + mtl)*16 + kn*4) * 512 + rem*16;
                uint32_t dst = bufb2 + mtl * 2048 + rem * 16;
                CP_ASYNC(dst, src);
                CP_ASYNC(dst + 8192, src + XA_TERM);
            }
            #pragma unroll
            for (int q = 0; q < 4; q++) {
                int idx = q * 256 + t;
                const unsigned char* src = g_tb + kn * 16384 + idx * 16;
                uint32_t dst = bufb2 + 16384 + idx * 16;
                CP_ASYNC(dst, src);
                CP_ASYNC(dst + 16384, src + TB_TERM);
            }
        }
        CP_COMMIT();
    }

    // ---- epilogue: h tile to smem + e1/e2 partials ----
    __syncthreads();
    float* hs   = (float*)smem;              // 64 x 128 fp32 = 32KB
    float* ered = (float*)(smem + 32768);    // [64][2cg][2] floats
    const int r0 = rg * 16 + g, r1 = r0 + 8;
    float s1a = 0.f, s2a = 0.f, s1b = 0.f, s2b = 0.f;
    #pragma unroll
    for (int td = 0; td < 8; td++) {
        const int cb = cg * 64 + td * 8 + q2;
        hs[r0 * 128 + cb]     = c_[td][0];
        hs[r0 * 128 + cb + 1] = c_[td][1];
        hs[r1 * 128 + cb]     = c_[td][2];
        hs[r1 * 128 + cb + 1] = c_[td][3];
        const float w10 = __ldg(aw + cb), w11 = __ldg(aw + cb + 1);
        const float w20 = __ldg(aw + FOUT + cb), w21 = __ldg(aw + FOUT + cb + 1);
        s1a += c_[td][0] * w10 + c_[td][1] * w11;
        s2a += c_[td][0] * w20 + c_[td][1] * w21;
        s1b += c_[td][2] * w10 + c_[td][3] * w11;
        s2b += c_[td][2] * w20 + c_[td][3] * w21;
    }
    #pragma unroll
    for (int o = 1; o <= 2; o <<= 1) {
        s1a += __shfl_xor_sync(0xFFFFFFFFu, s1a, o);
        s2a += __shfl_xor_sync(0xFFFFFFFFu, s2a, o);
        s1b += __shfl_xor_sync(0xFFFFFFFFu, s1b, o);
        s2b += __shfl_xor_sync(0xFFFFFFFFu, s2b, o);
    }
    if (qh == 0) {
        ered[r0 * 4 + cg * 2]     = s1a;
        ered[r0 * 4 + cg * 2 + 1] = s2a;
        ered[r1 * 4 + cg * 2]     = s1b;
        ered[r1 * 4 + cg * 2 + 1] = s2b;
    }
    __syncthreads();

    // ---- build remapped fp16 B tile (k_prep logic, smem source) ----
    unsigned char* tb = g_bt + (size_t)bx * TILE_BYTES;
    #pragma unroll
    for (int i = 0; i < 4; i++) {
        int rho = i * 256 + t;
        int blk = rho >> 3, dr = rho & 7;
        int kk = blk & 1, dn = (blk >> 1) & 1, dp8 = (blk >> 2) & 7, st = blk >> 5;
        int d  = dp8 * 16 + dn * 8 + dr;
        int jb = st * 16 + kk * 2;
        uint32_t h4[4];
        #pragma unroll
        for (int m = 0; m < 4; m++)
            h4[m] = pack16(hs[(jb + 4*m) * 128 + d], hs[(jb + 4*m + 1) * 128 + d]);
        *(uint4*)(tb + (uint32_t)blk * 128 + dr * 16) =
            make_uint4(h4[0], h4[1], h4[2], h4[3]);
    }
    if (t < 64) {
        g_e1s[bx * 64 + t] = (ered[t * 4]     + ered[t * 4 + 2]) * L2E;
        g_e2s[bx * 64 + t] = (ered[t * 4 + 1] + ered[t * 4 + 3]) * L2E;
    }
}

// ---------------------------------------------------------------------------
// Kernel 3 (main): fused masked-exp + fp16 HMMA attention GEMM (R11), grid
// rebalanced to exactly 148 CTAs: grid (37,4); bx<36 -> 224 rows (14 groups),
// bx==36 -> 128 rows (8 groups). Inactive warps do copies/syncs only.
// ---------------------------------------------------------------------------
__global__ __launch_bounds__(512, 1) void k_main(const int* __restrict__ adj)
{
    extern __shared__ unsigned char smem[];
    const uint32_t sb = smem_u32(smem);
    const int t = threadIdx.x, w = t >> 5, l = t & 31;
    const int bx = blockIdx.x, by = blockIdx.y;
    const int g = l >> 2, qh = l & 3, q2 = qh * 2;
    const int nrg = (bx == 36) ? 8 : 14;
    const bool act = (w < nrg);
    const int rowb = bx * 224 + w * 16;
    const size_t jbase = (size_t)by * JBLK;

    // prime B double-buffer (2 x 16KB)
    const unsigned char* bt0 = g_bt + (size_t)(by * NCH) * TILE_BYTES;
    #pragma unroll
    for (int c = 0; c < 2; c++) {
        uint32_t dst = sb + c * TILE_BYTES + t * 16;
        const unsigned char* src = bt0 + (size_t)c * TILE_BYTES + t * 16;
        CP_ASYNC(dst, src);
        CP_ASYNC(dst + 8192, src + 8192);
        CP_COMMIT();
    }

    float se1g = 0.f, se1h = 0.f;
    const int* pg = adj;
    const int* ph = adj;
    int4 avg = make_int4(0,0,0,0), avh = make_int4(0,0,0,0);
    int joff = 4 * qh;
    if (act) {
        se1g = g_e1s[rowb + g];
        se1h = g_e1s[rowb + g + 8];
        pg = adj + (size_t)(rowb + g) * NN + jbase;
        ph = adj + (size_t)(rowb + g + 8) * NN + jbase;
        avg = __ldg((const int4*)(pg + joff));
        avh = __ldg((const int4*)(ph + joff));
    }

    float c_[16][4];
    #pragma unroll
    for (int td = 0; td < 16; td++)
        #pragma unroll
        for (int k = 0; k < 4; k++) c_[td][k] = 0.f;
    float crs[4] = {0.f, 0.f, 0.f, 0.f};
    const uint32_t bones[2] = {0x3C003C00u, 0x3C003C00u};

    for (int c = 0; c < NCH; c++) {
        CP_WAIT1();
        __syncthreads();
        const uint32_t bufb = sb + (c & 1) * TILE_BYTES;

        if (act) {
            #pragma unroll
            for (int s = 0; s < 4; s++) {
                const float4 ev = *(const float4*)(g_e2s + jbase + joff);

                const int4 bg = avg, bh_ = avh;
                if (!(c == NCH - 1 && s == 3)) {
                    joff += 16;
                    avg = __ldg((const int4*)(pg + joff));
                    avh = __ldg((const int4*)(ph + joff));
                }

                float pa0 = pcalc(se1g, ev.x), pa1 = pcalc(se1g, ev.y);
                float pa2 = pcalc(se1g, ev.z), pa3 = pcalc(se1g, ev.w);
                float pb0 = pcalc(se1h, ev.x), pb1 = pcalc(se1h, ev.y);
                float pb2 = pcalc(se1h, ev.z), pb3 = pcalc(se1h, ev.w);

                uint32_t a[4];
                a[0] = packmask(pa0, pa1, bg.x, bg.y);
                a[1] = packmask(pb0, pb1, bh_.x, bh_.y);
                a[2] = packmask(pa2, pa3, bg.z, bg.w);
                a[3] = packmask(pb2, pb3, bh_.z, bh_.w);

                #pragma unroll
                for (int dp = 0; dp < 8; dp++) {
                    uint32_t bh[4];
                    const uint32_t ad = bufb + (s * 8 + dp) * 512
                                      + (l >> 3) * 128 + (l & 7) * 16;
                    LDMX4(bh, ad);
                    mma16816(c_[2 * dp],     a, bh);
                    mma16816(c_[2 * dp + 1], a, bh + 2);
                }
                mma16816(crs, a, bones);
            }
        }

        __syncthreads();
        if (c + 2 < NCH) {
            uint32_t dst = sb + (c & 1) * TILE_BYTES + t * 16;
            const unsigned char* src = bt0 + (size_t)(c + 2) * TILE_BYTES + t * 16;
            CP_ASYNC(dst, src);
            CP_ASYNC(dst + 8192, src + 8192);
        }
        CP_COMMIT();
    }

    if (act) {
        if (qh == 0) {
            g_psum[by][rowb + g]     = crs[0];
            g_psum[by][rowb + g + 8] = crs[2];
        }
        float* pb = g_part[by];
        #pragma unroll
        for (int td = 0; td < 16; td++) {
            const int col = td * 8 + q2;
            *(float2*)(pb + (size_t)(rowb + g) * FOUT + col) =
                make_float2(c_[td][0], c_[td][1]);
            *(float2*)(pb + (size_t)(rowb + g + 8) * FOUT + col) =
                make_float2(c_[td][2], c_[td][3]);
        }
    }
}

// ---------------------------------------------------------------------------
// Kernel 4 (final): combine j-split partials, normalize, fast ELU.
// ---------------------------------------------------------------------------
__global__ __launch_bounds__(256) void k_final(float* __restrict__ out)
{
    const int idx = blockIdx.x * 256 + threadIdx.x;   // float4 index
    const int r = idx >> 5;
    float4 v = make_float4(0.f, 0.f, 0.f, 0.f);
    #pragma unroll
    for (int p = 0; p < JSPLIT; p++) {
        float4 a = ((const float4*)g_part[p])[idx];
        v.x += a.x; v.y += a.y; v.z += a.z; v.w += a.w;
    }
    const float inv = 1.f / (g_psum[0][r] + g_psum[1][r] + g_psum[2][r] + g_psum[3][r]);
    float o[4] = { v.x * inv, v.y * inv, v.z * inv, v.w * inv };
    #pragma unroll
    for (int i = 0; i < 4; i++)
        o[i] = o[i] > 0.f ? o[i] : (ex2f(o[i] * L2E) - 1.f);
    ((float4*)out)[idx] = make_float4(o[0], o[1], o[2], o[3]);
}

// ---------------------------------------------------------------------------
extern "C" void kernel_launch(void* const* d_in, const int* in_sizes, int n_in,
                              void* d_out, int out_size)
{
    const float* x     = (const float*)d_in[0];
    const int*   adj   = (const int*)d_in[1];
    const float* trans = (const float*)d_in[2];
    const float* aw    = (const float*)d_in[3];
    float*       out   = (float*)d_out;

    cudaFuncSetAttribute(k_hgemm, cudaFuncAttributeMaxDynamicSharedMemorySize, 2 * HB);
    cudaFuncSetAttribute(k_main,  cudaFuncAttributeMaxDynamicSharedMemorySize, 2 * TILE_BYTES);

    k_cvt<<<528, 256>>>(x, trans);
    k_hgemm<<<128, 256, 2 * HB>>>(aw);
    dim3 gmain(37, JSPLIT);
    k_main<<<gmain, 512, 2 * TILE_BYTES>>>(adj);
    k_final<<<NN * FOUT / (256 * 4), 256>>>(out);
}